// round 2
// baseline (speedup 1.0000x reference)
#include <cuda_runtime.h>
#include <cuda_bf16.h>
#include <math.h>

// ---------------------------------------------------------------------------
// ChannelCrossAttention  (XCA, cross-stream):
//   qkv = x @ Wqkv  -> (q,k,v) in (B,H,d,N) layout, d=64, N=4096
//   logits = (q@k^T)/(|q||k|) * temp  (64x64 per (b,h)), softmax, out = P@v
//   y = out @ Wproj + b
// Streams cross: out_rgb uses q_rgb with k_T,v_T;  out_T uses q_T with k_rgb,v_rgb.
// ---------------------------------------------------------------------------

#define BDIM   8
#define NTOK   4096
#define CDIM   512
#define HEADS  8
#define DH     64

// scratch: qkv[s][w][b][h*64+d][n]   s=stream, w=q/k/v
__device__ float g_qkv[2u * 3u * 8u * 512u * 4096u];   // 402 MB
// attention output, [s][b][k=h*64+d][n]
__device__ float g_att[2u * 8u * 512u * 4096u];        // 134 MB

// ---------------------------------------------------------------------------
// Kernel 1: qkv = X @ W (K=512 -> 1536), scatter to (B,H,d,N) layout.
// Output tile: rows = output channel c (128), cols = token m (128).
// ---------------------------------------------------------------------------
__global__ __launch_bounds__(256) void qkv_gemm_kernel(
    const float* __restrict__ x, const float* __restrict__ x_d,
    const float* __restrict__ Wr, const float* __restrict__ Wt)
{
    const int s  = blockIdx.z;
    const float* __restrict__ X = s ? x_d : x;
    const float* __restrict__ W = s ? Wt  : Wr;

    const int m0 = blockIdx.x * 128;     // token index (b*4096+n)
    const int c0 = blockIdx.y * 128;     // output channel
    const int b  = m0 >> 12;
    const int n0 = m0 & 4095;

    __shared__ float Ws[16][128];
    __shared__ float Xs[16][128];

    const int tid = threadIdx.x;
    const int ty = tid >> 4;    // c-group
    const int tx = tid & 15;    // m-group

    float acc[8][8];
#pragma unroll
    for (int i = 0; i < 8; i++)
#pragma unroll
        for (int j = 0; j < 8; j++) acc[i][j] = 0.f;

    for (int k0 = 0; k0 < 512; k0 += 16) {
#pragma unroll
        for (int it = 0; it < 2; it++) {
            int idx = tid + it * 256;          // 0..511
            int kk = idx >> 5;
            int cq = idx & 31;
            float4 w4 = *(const float4*)&W[(size_t)(k0 + kk) * 1536 + c0 + cq * 4];
            *(float4*)&Ws[kk][cq * 4] = w4;
        }
#pragma unroll
        for (int it = 0; it < 2; it++) {
            int idx = tid + it * 256;
            int mm = idx >> 2;
            int kq = idx & 3;
            float4 x4 = *(const float4*)&X[(size_t)(m0 + mm) * 512 + k0 + kq * 4];
            Xs[kq * 4 + 0][mm] = x4.x;
            Xs[kq * 4 + 1][mm] = x4.y;
            Xs[kq * 4 + 2][mm] = x4.z;
            Xs[kq * 4 + 3][mm] = x4.w;
        }
        __syncthreads();
#pragma unroll
        for (int kk = 0; kk < 16; kk++) {
            float rc[8], rm[8];
#pragma unroll
            for (int i = 0; i < 8; i++) rc[i] = Ws[kk][ty * 8 + i];
#pragma unroll
            for (int j = 0; j < 8; j++) rm[j] = Xs[kk][tx * 8 + j];
#pragma unroll
            for (int i = 0; i < 8; i++)
#pragma unroll
                for (int j = 0; j < 8; j++) acc[i][j] += rc[i] * rm[j];
        }
        __syncthreads();
    }

    // epilogue: scatter into g_qkv[(s*3+which)][b][rem][n]
#pragma unroll
    for (int i = 0; i < 8; i++) {
        int c = c0 + ty * 8 + i;
        int which = c >> 9;           // 0=q 1=k 2=v
        int rem = c & 511;            // h*64+d
        size_t base = ((size_t)((s * 3 + which) * 8 + b)) * 2097152
                    + (size_t)rem * 4096 + n0 + tx * 8;
        float4 v0 = make_float4(acc[i][0], acc[i][1], acc[i][2], acc[i][3]);
        float4 v1 = make_float4(acc[i][4], acc[i][5], acc[i][6], acc[i][7]);
        *(float4*)&g_qkv[base]     = v0;
        *(float4*)&g_qkv[base + 4] = v1;
    }
}

// ---------------------------------------------------------------------------
// Kernel 2: per (s, b, h): Gram + norms + softmax + P@V.
//   s=0 -> out_rgb: q from stream0, k/v from stream1, temp_rgb
//   s=1 -> out_T  : q from stream1, k/v from stream0, temp_T
// ---------------------------------------------------------------------------
__global__ __launch_bounds__(256) void attn_kernel(
    const float* __restrict__ temp_rgb, const float* __restrict__ temp_T)
{
    const int s  = blockIdx.y;
    const int bh = blockIdx.x;
    const int b = bh >> 3;
    const int h = bh & 7;
    const int so = s ^ 1;

    const float* __restrict__ q = g_qkv + ((size_t)((s  * 3 + 0) * 8 + b)) * 2097152 + (size_t)h * 64 * 4096;
    const float* __restrict__ k = g_qkv + ((size_t)((so * 3 + 1) * 8 + b)) * 2097152 + (size_t)h * 64 * 4096;
    const float* __restrict__ v = g_qkv + ((size_t)((so * 3 + 2) * 8 + b)) * 2097152 + (size_t)h * 64 * 4096;
    const float temp = (s ? temp_T : temp_rgb)[h];

    __shared__ float bufA[64 * 65];
    __shared__ float bufB[64 * 65];
    __shared__ float qn[64], kn[64];

    const int tid = threadIdx.x;
    const int ty = tid >> 4;
    const int tx = tid & 15;

    float acc[4][4];
#pragma unroll
    for (int i = 0; i < 4; i++)
#pragma unroll
        for (int j = 0; j < 4; j++) acc[i][j] = 0.f;
    float nacc = 0.f;

    // -------- pass 1: G = q @ k^T over N, plus sum-of-squares per row ------
    for (int ch = 0; ch < 64; ch++) {
        const int nn0 = ch * 64;
#pragma unroll
        for (int it = 0; it < 4; it++) {
            int idx = tid + it * 256;       // 0..1023
            int r  = idx >> 4;
            int nq = idx & 15;
            float4 a4 = *(const float4*)&q[(size_t)r * 4096 + nn0 + nq * 4];
            bufA[r * 65 + nq * 4 + 0] = a4.x;
            bufA[r * 65 + nq * 4 + 1] = a4.y;
            bufA[r * 65 + nq * 4 + 2] = a4.z;
            bufA[r * 65 + nq * 4 + 3] = a4.w;
            float4 b4 = *(const float4*)&k[(size_t)r * 4096 + nn0 + nq * 4];
            bufB[r * 65 + nq * 4 + 0] = b4.x;
            bufB[r * 65 + nq * 4 + 1] = b4.y;
            bufB[r * 65 + nq * 4 + 2] = b4.z;
            bufB[r * 65 + nq * 4 + 3] = b4.w;
        }
        __syncthreads();
#pragma unroll 8
        for (int nn = 0; nn < 64; nn++) {
            float rq[4], rk[4];
#pragma unroll
            for (int i = 0; i < 4; i++) rq[i] = bufA[(ty * 4 + i) * 65 + nn];
#pragma unroll
            for (int j = 0; j < 4; j++) rk[j] = bufB[(tx * 4 + j) * 65 + nn];
#pragma unroll
            for (int i = 0; i < 4; i++)
#pragma unroll
                for (int j = 0; j < 4; j++) acc[i][j] += rq[i] * rk[j];
        }
        if (tid < 64) {
            float s2 = 0.f;
#pragma unroll 8
            for (int nn = 0; nn < 64; nn++) { float a = bufA[tid * 65 + nn]; s2 += a * a; }
            nacc += s2;
        } else if (tid < 128) {
            int r = tid - 64;
            float s2 = 0.f;
#pragma unroll 8
            for (int nn = 0; nn < 64; nn++) { float a = bufB[r * 65 + nn]; s2 += a * a; }
            nacc += s2;
        }
        __syncthreads();
    }

    if (tid < 64)       qn[tid]      = sqrtf(nacc);
    else if (tid < 128) kn[tid - 64] = sqrtf(nacc);
    // write Gram into bufB (ks no longer needed)
#pragma unroll
    for (int i = 0; i < 4; i++)
#pragma unroll
        for (int j = 0; j < 4; j++)
            bufB[(ty * 4 + i) * 65 + tx * 4 + j] = acc[i][j];
    __syncthreads();

    // -------- softmax over 64 cols, with norm + temperature fold ----------
    if (tid < 64) {
        const int i = tid;
        const float qi = fmaxf(qn[i], 1e-12f);
        float mx = -1e30f;
        for (int j = 0; j < 64; j++) {
            float val = bufB[i * 65 + j] * temp / (qi * fmaxf(kn[j], 1e-12f));
            bufB[i * 65 + j] = val;
            mx = fmaxf(mx, val);
        }
        float sum = 0.f;
        for (int j = 0; j < 64; j++) {
            float e = __expf(bufB[i * 65 + j] - mx);
            bufB[i * 65 + j] = e;
            sum += e;
        }
        float inv = 1.f / sum;
        for (int j = 0; j < 64; j++) bufB[i * 65 + j] *= inv;
    }
    __syncthreads();

    // -------- pass 2: out = P @ v, streamed over N -------------------------
    const size_t attbase = ((size_t)(s * 8 + b)) * 2097152;
    for (int ch = 0; ch < 64; ch++) {
        const int nn0 = ch * 64;
#pragma unroll
        for (int it = 0; it < 4; it++) {
            int idx = tid + it * 256;
            int r  = idx >> 4;
            int nq = idx & 15;
            float4 a4 = *(const float4*)&v[(size_t)r * 4096 + nn0 + nq * 4];
            bufA[r * 65 + nq * 4 + 0] = a4.x;
            bufA[r * 65 + nq * 4 + 1] = a4.y;
            bufA[r * 65 + nq * 4 + 2] = a4.z;
            bufA[r * 65 + nq * 4 + 3] = a4.w;
        }
        __syncthreads();
        float o[4][4];
#pragma unroll
        for (int i = 0; i < 4; i++)
#pragma unroll
            for (int j = 0; j < 4; j++) o[i][j] = 0.f;
#pragma unroll 8
        for (int j = 0; j < 64; j++) {
            float p[4], vv[4];
#pragma unroll
            for (int ii = 0; ii < 4; ii++) p[ii] = bufB[(ty * 4 + ii) * 65 + j];
#pragma unroll
            for (int jj = 0; jj < 4; jj++) vv[jj] = bufA[j * 65 + tx * 4 + jj];
#pragma unroll
            for (int ii = 0; ii < 4; ii++)
#pragma unroll
                for (int jj = 0; jj < 4; jj++) o[ii][jj] += p[ii] * vv[jj];
        }
#pragma unroll
        for (int ii = 0; ii < 4; ii++) {
            int d = ty * 4 + ii;
            size_t addr = attbase + (size_t)(h * 64 + d) * 4096 + nn0 + tx * 4;
            float4 w4 = make_float4(o[ii][0], o[ii][1], o[ii][2], o[ii][3]);
            *(float4*)&g_att[addr] = w4;
        }
        __syncthreads();
    }
}

// ---------------------------------------------------------------------------
// Kernel 3: y = att^T @ Wproj + bias.   att stored [k=512][n=4096] per (s,b).
// ---------------------------------------------------------------------------
__global__ __launch_bounds__(256) void proj_gemm_kernel(
    const float* __restrict__ Wr, const float* __restrict__ br,
    const float* __restrict__ Wt, const float* __restrict__ bt,
    float* __restrict__ out)
{
    const int z = blockIdx.z;
    const int s = z >> 3;
    const int b = z & 7;
    const float* __restrict__ W    = s ? Wt : Wr;
    const float* __restrict__ bias = s ? bt : br;
    const float* __restrict__ A = g_att + ((size_t)(s * 8 + b)) * 2097152;

    const int m0 = blockIdx.x * 128;   // n
    const int c0 = blockIdx.y * 128;   // output channel

    __shared__ float As[16][128];
    __shared__ float Ws2[16][128];

    const int tid = threadIdx.x;
    const int ty = tid >> 4;   // m-group
    const int tx = tid & 15;   // c-group

    float acc[8][8];
#pragma unroll
    for (int i = 0; i < 8; i++)
#pragma unroll
        for (int j = 0; j < 8; j++) acc[i][j] = 0.f;

    for (int k0 = 0; k0 < 512; k0 += 16) {
#pragma unroll
        for (int it = 0; it < 2; it++) {
            int idx = tid + it * 256;
            int kk = idx >> 5;
            int mq = idx & 31;
            *(float4*)&As[kk][mq * 4]  = *(const float4*)&A[(size_t)(k0 + kk) * 4096 + m0 + mq * 4];
            *(float4*)&Ws2[kk][mq * 4] = *(const float4*)&W[(size_t)(k0 + kk) * 512 + c0 + mq * 4];
        }
        __syncthreads();
#pragma unroll
        for (int kk = 0; kk < 16; kk++) {
            float rm[8], rc[8];
#pragma unroll
            for (int i = 0; i < 8; i++) rm[i] = As[kk][ty * 8 + i];
#pragma unroll
            for (int j = 0; j < 8; j++) rc[j] = Ws2[kk][tx * 8 + j];
#pragma unroll
            for (int i = 0; i < 8; i++)
#pragma unroll
                for (int j = 0; j < 8; j++) acc[i][j] += rm[i] * rc[j];
        }
        __syncthreads();
    }

    float bj[8];
#pragma unroll
    for (int j = 0; j < 8; j++) bj[j] = bias[c0 + tx * 8 + j];

    const size_t obase = (size_t)s * 16777216 + (size_t)b * 4096 * 512;
#pragma unroll
    for (int i = 0; i < 8; i++) {
        int n = m0 + ty * 8 + i;
        size_t row = obase + (size_t)n * 512 + c0 + tx * 8;
        float4 v0 = make_float4(acc[i][0] + bj[0], acc[i][1] + bj[1],
                                acc[i][2] + bj[2], acc[i][3] + bj[3]);
        float4 v1 = make_float4(acc[i][4] + bj[4], acc[i][5] + bj[5],
                                acc[i][6] + bj[6], acc[i][7] + bj[7]);
        *(float4*)&out[row]     = v0;
        *(float4*)&out[row + 4] = v1;
    }
}

// ---------------------------------------------------------------------------
extern "C" void kernel_launch(void* const* d_in, const int* in_sizes, int n_in,
                              void* d_out, int out_size)
{
    const float* x        = (const float*)d_in[0];
    const float* x_d      = (const float*)d_in[1];
    const float* W_qkv_r  = (const float*)d_in[2];
    const float* W_qkv_T  = (const float*)d_in[3];
    const float* temp_r   = (const float*)d_in[4];
    const float* temp_T   = (const float*)d_in[5];
    const float* W_proj_r = (const float*)d_in[6];
    const float* b_proj_r = (const float*)d_in[7];
    const float* W_proj_T = (const float*)d_in[8];
    const float* b_proj_T = (const float*)d_in[9];
    float* out = (float*)d_out;

    // 1) QKV GEMMs (both streams)
    {
        dim3 grid(256, 12, 2);   // m tiles (32768/128), c tiles (1536/128), stream
        qkv_gemm_kernel<<<grid, 256>>>(x, x_d, W_qkv_r, W_qkv_T);
    }
    // 2) Cross attention per (s, b, h)
    {
        dim3 grid(64, 2);
        attn_kernel<<<grid, 256>>>(temp_r, temp_T);
    }
    // 3) Projection + bias -> d_out
    {
        dim3 grid(32, 4, 16);    // n tiles, c tiles, s*b
        proj_gemm_kernel<<<grid, 256>>>(W_proj_r, b_proj_r, W_proj_T, b_proj_T, out);
    }
}